// round 3
// baseline (speedup 1.0000x reference)
#include <cuda_runtime.h>
#include <math.h>
#include <stdint.h>

// Problem constants (from reference)
#define NMAX 200000
#define EMAX 8192
#define H    64
#define TE   32
#define EA   32
#define DF   128
#define FEAT (2*H + EA + TE)   // 192

// ---------------- device-global scratch (allowed; no allocation) ----------------
__device__ float g_h[(size_t)NMAX * H];     // node memory
__device__ float g_c[(size_t)NMAX * H];     // LSTM cell state
__device__ int   g_head[NMAX];              // per-node endpoint list head
__device__ int   g_seq[NMAX];               // per-node sequence counter (lock)
__device__ int   g_link[2 * EMAX];          // endpoint linked list
__device__ int   g_rank[2 * EMAX];          // rank of endpoint within its node's event order
__device__ int   g_ctr;                     // event claim counter

// ---------------- memory-order helpers ----------------
__device__ __forceinline__ int ld_acq(const int* p) {
    int v;
    asm volatile("ld.acquire.gpu.b32 %0, [%1];" : "=r"(v) : "l"(p) : "memory");
    return v;
}
__device__ __forceinline__ void st_rel(int* p, int v) {
    asm volatile("st.release.gpu.b32 [%0], %1;" :: "l"(p), "r"(v) : "memory");
}
__device__ __forceinline__ float sigm(float x) { return 1.0f / (1.0f + expf(-x)); }

// ---------------- K0: init touched-node state ----------------
__global__ void k_init(const int* __restrict__ ei, int E) {
    int s = blockIdx.x * blockDim.x + threadIdx.x;
    if (s == 0) g_ctr = 0;
    if (s >= 2 * E) return;
    int v = ei[s];                 // ei is [2,E] contiguous: s<E -> src, else dst
    g_head[v] = -1;
    g_seq[v]  = 0;
    float4 z4 = make_float4(0.f, 0.f, 0.f, 0.f);
    float4* hp = (float4*)&g_h[(size_t)v * H];
    float4* cp = (float4*)&g_c[(size_t)v * H];
#pragma unroll
    for (int i = 0; i < H / 4; i++) { hp[i] = z4; cp[i] = z4; }
}

// ---------------- K1: build per-node endpoint linked lists ----------------
__global__ void k_link(const int* __restrict__ ei, int E) {
    int s = blockIdx.x * blockDim.x + threadIdx.x;
    if (s >= 2 * E) return;
    g_link[s] = atomicExch(&g_head[ei[s]], s);
}

// ---------------- K2: assign deterministic ranks (per-node event order) ----------------
__global__ void k_rank(const int* __restrict__ ei, int E) {
    int s = blockIdx.x * blockDim.x + threadIdx.x;
    if (s >= 2 * E) return;
    int v = ei[s];
    if (g_head[v] != s) return;    // exactly one thread owns each node's list
    for (int a = s; a >= 0; a = g_link[a]) {
        int ka = (a < E) ? (a << 1) : (((a - E) << 1) | 1);
        int r = 0;
        for (int b = s; b >= 0; b = g_link[b]) {
            int kb = (b < E) ? (b << 1) : (((b - E) << 1) | 1);
            r += (kb < ka);
        }
        g_rank[a] = r;
    }
}

// ---------------- K3: persistent event-processing kernel ----------------
__global__ void __launch_bounds__(128, 4) k_events(
    const int*   __restrict__ ei,
    const float* __restrict__ eattr,
    const float* __restrict__ etime,
    const float* __restrict__ time_w,
    const float* __restrict__ time_b,
    const float* __restrict__ W_msg,   // [192,64]
    const float* __restrict__ b_msg,   // [64]
    const float* __restrict__ W_ih,    // [64,256]
    const float* __restrict__ W_hh,    // [64,256]
    const float* __restrict__ b_lstm,  // [256]
    int E)
{
    __shared__ __align__(16) float sh_feat[2][FEAT];  // row0=[hd|hs|ea|te], row1=[hs|hd|ea|te]
    __shared__ __align__(16) float sh_c[2][H];
    __shared__ __align__(16) float sh_m[2][H];
    __shared__ __align__(16) float sh_g[2][4 * H];
    __shared__ int sh_ev;
    const int tid = threadIdx.x;

    for (;;) {
        if (tid == 0) sh_ev = atomicAdd(&g_ctr, 1);
        __syncthreads();
        const int e = sh_ev;
        if (e >= E) return;

        const int s  = ei[e];
        const int d  = ei[E + e];
        const int rs = g_rank[e];
        const int rd = g_rank[E + e];

        // wait until all earlier events touching s and d have published
        if (tid == 0) {
            while (ld_acq(&g_seq[s]) != rs) { __nanosleep(32); }
            if (d != s) {
                while (ld_acq(&g_seq[d]) != rd) { __nanosleep(32); }
            }
        }
        __syncthreads();

        // stage inputs into shared memory
        if (tid < H) {
            float hs = g_h[(size_t)s * H + tid];
            float hd = g_h[(size_t)d * H + tid];
            sh_feat[0][tid]     = hd;  sh_feat[0][H + tid] = hs;   // msg for src: [hd, hs, ...]
            sh_feat[1][tid]     = hs;  sh_feat[1][H + tid] = hd;   // msg for dst: [hs, hd, ...]
            sh_c[0][tid] = g_c[(size_t)s * H + tid];
            sh_c[1][tid] = g_c[(size_t)d * H + tid];
        } else {
            int j = tid - H;
            if (j < EA) {
                float a = eattr[(size_t)e * EA + j];
                sh_feat[0][2 * H + j] = a;  sh_feat[1][2 * H + j] = a;
            } else {
                int k = j - EA;               // 0..31
                float t   = etime[e];
                float arg = fmaf(t, time_w[k], time_b[k]);   // match XLA fma contraction
                float te  = (float)cos((double)arg);         // exact range reduction (|arg| up to ~3e4)
                sh_feat[0][2 * H + EA + k] = te;  sh_feat[1][2 * H + EA + k] = te;
            }
        }
        __syncthreads();

        // message GEMV: m[r][q] = relu(feat[r] @ W_msg[:,q] + b_msg[q])
        // 128 threads: r = tid>>6 (row), q = tid&63 (column). In-bounds, race-free.
        {
            int r = tid >> 6, q = tid & 63;
            float acc = b_msg[q];
            const float* frow = sh_feat[r];
#pragma unroll 8
            for (int k = 0; k < FEAT; k++) {
                acc = fmaf(frow[k], W_msg[k * H + q], acc);
            }
            sh_m[r][q] = fmaxf(acc, 0.f);
        }
        __syncthreads();

        // gates: g[r] = m[r]@W_ih + hp[r]@W_hh + b ; 128 threads, 4 cols each
        {
            int r = tid >> 6, q = tid & 63;     // cols 4q..4q+3 of 256
            float4 acc = ((const float4*)b_lstm)[q];
            const float4* __restrict__ Wi = (const float4*)W_ih;   // [64][64]
            const float4* __restrict__ Wh = (const float4*)W_hh;
            const float* mrow = sh_m[r];
            const float* hrow = &sh_feat[r][H];   // hp[0]=hs, hp[1]=hd
#pragma unroll 4
            for (int k = 0; k < H; k++) {
                float  mv = mrow[k], hv = hrow[k];
                float4 wi = Wi[k * 64 + q];
                float4 wh = Wh[k * 64 + q];
                acc.x = fmaf(mv, wi.x, fmaf(hv, wh.x, acc.x));
                acc.y = fmaf(mv, wi.y, fmaf(hv, wh.y, acc.y));
                acc.z = fmaf(mv, wi.z, fmaf(hv, wh.z, acc.z));
                acc.w = fmaf(mv, wi.w, fmaf(hv, wh.w, acc.w));
            }
            ((float4*)sh_g[r])[q] = acc;
        }
        __syncthreads();

        // LSTM elementwise + writeback
        {
            int r = tid >> 6, j = tid & 63;
            float gi = sh_g[r][j];
            float gf = sh_g[r][H + j];
            float gg = sh_g[r][2 * H + j];
            float go = sh_g[r][3 * H + j];
            float cn = sigm(gf) * sh_c[r][j] + sigm(gi) * tanhf(gg);
            float hn = sigm(go) * tanhf(cn);
            if (r == 1 || d != s) {             // src==dst: dst row wins (rows identical anyway)
                int node = r ? d : s;
                g_h[(size_t)node * H + j] = hn;
                g_c[(size_t)node * H + j] = cn;
            }
        }
        __syncthreads();

        // publish
        if (tid == 0) {
            __threadfence();
            if (d == s) {
                st_rel(&g_seq[s], rs + 2);
            } else {
                st_rel(&g_seq[s], rs + 1);
                st_rel(&g_seq[d], rd + 1);
            }
        }
    }
}

// ---------------- K4: embedding + classifier for dst nodes of each edge ----------------
__global__ void k_logits(
    const float* __restrict__ x,
    const int*   __restrict__ ei,
    const float* __restrict__ W_emb,   // [192,64]
    const float* __restrict__ b_emb,   // [64]
    const float* __restrict__ W_cls,   // [64,A]
    const float* __restrict__ b_cls,   // [A]
    float*       __restrict__ out,
    int E, int A)
{
    __shared__ float sh_h[H];
    __shared__ float sh_x[DF];
    __shared__ float sh_z[H];
    int e = blockIdx.x, tid = threadIdx.x;   // 64 threads
    int d = ei[E + e];
    sh_h[tid]     = g_h[(size_t)d * H + tid];
    sh_x[tid]     = x[(size_t)d * DF + tid];
    sh_x[H + tid] = x[(size_t)d * DF + H + tid];
    __syncthreads();

    float acc = b_emb[tid];
#pragma unroll 4
    for (int k = 0; k < H; k++)  acc = fmaf(sh_h[k], W_emb[k * H + tid], acc);
#pragma unroll 4
    for (int k = 0; k < DF; k++) acc = fmaf(sh_x[k], W_emb[(H + k) * H + tid], acc);
    sh_z[tid] = acc;
    __syncthreads();

    if (tid < A) {
        float a = b_cls[tid];
#pragma unroll 4
        for (int k = 0; k < H; k++) a = fmaf(sh_z[k], W_cls[k * A + tid], a);
        out[(size_t)e * A + tid] = a;
    }
}

// ---------------- launch ----------------
extern "C" void kernel_launch(void* const* d_in, const int* in_sizes, int n_in,
                              void* d_out, int out_size)
{
    const float* x      = (const float*)d_in[0];
    const int*   ei     = (const int*)  d_in[1];   // [2,E]
    const float* eattr  = (const float*)d_in[2];
    const float* etime  = (const float*)d_in[3];
    const float* time_w = (const float*)d_in[4];
    const float* time_b = (const float*)d_in[5];
    const float* W_msg  = (const float*)d_in[6];
    const float* b_msg  = (const float*)d_in[7];
    const float* W_ih   = (const float*)d_in[8];
    const float* W_hh   = (const float*)d_in[9];
    const float* b_lstm = (const float*)d_in[10];
    const float* W_emb  = (const float*)d_in[11];
    const float* b_emb  = (const float*)d_in[12];
    const float* W_cls  = (const float*)d_in[13];
    const float* b_cls  = (const float*)d_in[14];

    const int E = in_sizes[3];             // edge_time element count
    const int A = out_size / E;            // num classes
    const int twoE = 2 * E;
    const int thr = 256;
    const int blks = (twoE + thr - 1) / thr;

    // Persistent-kernel grid: MUST be fully co-resident for the claim/spin
    // scheduler's forward-progress guarantee. Query the actual device instead
    // of hard-coding an SM count. These are non-stream host queries — legal
    // during graph capture; the resulting grid dim is baked into the graph.
    int dev = 0, nsm = 0, occ = 0;
    cudaGetDevice(&dev);
    cudaDeviceGetAttribute(&nsm, cudaDevAttrMultiProcessorCount, dev);
    cudaOccupancyMaxActiveBlocksPerMultiprocessor(&occ, k_events, 128, 0);
    if (nsm <= 0) nsm = 1;
    if (occ <= 0) occ = 1;
    int nblk = nsm * occ;
    if (nblk > twoE) nblk = twoE;          // more blocks than events is pointless

    k_init<<<blks, thr>>>(ei, E);
    k_link<<<blks, thr>>>(ei, E);
    k_rank<<<blks, thr>>>(ei, E);
    k_events<<<nblk, 128>>>(ei, eattr, etime, time_w, time_b,
                            W_msg, b_msg, W_ih, W_hh, b_lstm, E);
    k_logits<<<E, 64>>>(x, ei, W_emb, b_emb, W_cls, b_cls, (float*)d_out, E, A);
}

// round 5
// speedup vs baseline: 1.3146x; 1.3146x over previous
#include <cuda_runtime.h>
#include <math.h>
#include <stdint.h>

// Problem constants (from reference)
#define NMAX 200000
#define EMAX 8192
#define H    64
#define TE   32
#define EA   32
#define DF   128
#define FEAT (2*H + EA + TE)   // 192
#define AMAX 64

// ---------------- device-global scratch (allowed; no allocation) ----------------
__device__ float g_h[(size_t)NMAX * H];     // node memory
__device__ float g_c[(size_t)NMAX * H];     // LSTM cell state
__device__ int   g_head[NMAX];              // per-node endpoint list head
__device__ int   g_seq[NMAX];               // per-node sequence counter (lock)
__device__ int   g_link[2 * EMAX];          // endpoint linked list
__device__ int   g_rank[2 * EMAX];          // rank of endpoint within its node's event order
__device__ float g_W1[FEAT * AMAX];         // fused W_emb @ W_cls
__device__ float g_b1[AMAX];                // fused bias

// ---------------- memory-order helpers ----------------
__device__ __forceinline__ int ld_acq(const int* p) {
    int v;
    asm volatile("ld.acquire.gpu.b32 %0, [%1];" : "=r"(v) : "l"(p) : "memory");
    return v;
}
__device__ __forceinline__ void st_rel(int* p, int v) {
    asm volatile("st.release.gpu.b32 [%0], %1;" :: "l"(p), "r"(v) : "memory");
}
__device__ __forceinline__ float sigm(float x) { return 1.0f / (1.0f + expf(-x)); }

// ---------------- K0: init touched-node state ----------------
__global__ void k_init(const int* __restrict__ ei, int E) {
    int s = blockIdx.x * blockDim.x + threadIdx.x;
    if (s >= 2 * E) return;
    int v = ei[s];                 // ei is [2,E] contiguous: s<E -> src, else dst
    g_head[v] = -1;
    g_seq[v]  = 0;
    float4 z4 = make_float4(0.f, 0.f, 0.f, 0.f);
    float4* hp = (float4*)&g_h[(size_t)v * H];
    float4* cp = (float4*)&g_c[(size_t)v * H];
#pragma unroll
    for (int i = 0; i < H / 4; i++) { hp[i] = z4; cp[i] = z4; }
}

// ---------------- K1: build per-node endpoint linked lists ----------------
__global__ void k_link(const int* __restrict__ ei, int E) {
    int s = blockIdx.x * blockDim.x + threadIdx.x;
    if (s >= 2 * E) return;
    g_link[s] = atomicExch(&g_head[ei[s]], s);
}

// ---------------- K2: assign deterministic ranks (per-node event order) ----------------
__global__ void k_rank(const int* __restrict__ ei, int E) {
    int s = blockIdx.x * blockDim.x + threadIdx.x;
    if (s >= 2 * E) return;
    int v = ei[s];
    if (g_head[v] != s) return;    // exactly one thread owns each node's list
    for (int a = s; a >= 0; a = g_link[a]) {
        int ka = (a < E) ? (a << 1) : (((a - E) << 1) | 1);
        int r = 0;
        for (int b = s; b >= 0; b = g_link[b]) {
            int kb = (b < E) ? (b << 1) : (((b - E) << 1) | 1);
            r += (kb < ka);
        }
        g_rank[a] = r;
    }
}

// ---------------- K2b: fuse classifier weights: W1 = W_emb @ W_cls, b1 = b_emb@W_cls + b_cls
__global__ void k_fuse(const float* __restrict__ W_emb,   // [192,64]
                       const float* __restrict__ b_emb,   // [64]
                       const float* __restrict__ W_cls,   // [64,A]
                       const float* __restrict__ b_cls,   // [A]
                       int A)
{
    int gid = blockIdx.x * blockDim.x + threadIdx.x;
    int total = FEAT * A;
    if (gid < total) {
        int k = gid / A, a = gid % A;
        float s0 = 0.f, s1 = 0.f;
#pragma unroll 8
        for (int j = 0; j < H; j += 2) {
            s0 = fmaf(W_emb[k * H + j],     W_cls[j * A + a],       s0);
            s1 = fmaf(W_emb[k * H + j + 1], W_cls[(j + 1) * A + a], s1);
        }
        g_W1[k * A + a] = s0 + s1;
    }
    if (gid < A) {
        float s = b_cls[gid];
#pragma unroll 8
        for (int j = 0; j < H; j++) s = fmaf(b_emb[j], W_cls[j * A + gid], s);
        g_b1[gid] = s;
    }
}

// ---------------- K3: persistent event-processing kernel (static round-robin) ----------------
__global__ void __launch_bounds__(128) k_events(
    const int*   __restrict__ ei,
    const float* __restrict__ eattr,
    const float* __restrict__ etime,
    const float* __restrict__ time_w,
    const float* __restrict__ time_b,
    const float* __restrict__ W_msg,   // [192,64]
    const float* __restrict__ b_msg,   // [64]
    const float* __restrict__ W_ih,    // [64,256]
    const float* __restrict__ W_hh,    // [64,256]
    const float* __restrict__ b_lstm,  // [256]
    int E, int nblk)
{
    __shared__ __align__(16) float sh_feat[2][FEAT];   // row0=[hd|hs|ea|te], row1=[hs|hd|ea|te]
    __shared__ __align__(16) float sh_c[2][H];
    __shared__ __align__(16) float sh_m[2][H];
    __shared__ __align__(16) float sh_part[4][2][H];   // msg partials per k-quarter
    __shared__ __align__(16) float sh_g[2][4 * H];
    const int tid = threadIdx.x;

    const float2* __restrict__ Wm2 = (const float2*)W_msg;   // [192][32] float2
    const float2* __restrict__ Wi2 = (const float2*)W_ih;    // [64][128] float2
    const float2* __restrict__ Wh2 = (const float2*)W_hh;
    const float2* __restrict__ Bl2 = (const float2*)b_lstm;

    // Static assignment: block b handles events b, b+nblk, b+2*nblk, ...
    // No atomics. Forward progress: deps are strictly earlier events; every
    // event's owner block is resident and processes its list in order, so the
    // minimal incomplete event always has all deps complete and finishes.
    for (int e = blockIdx.x; e < E; e += nblk) {
        const int s  = ei[e];
        const int d  = ei[E + e];
        const int rs = g_rank[e];
        const int rd = g_rank[E + e];

        // wait until all earlier events touching s and d have published
        if (tid == 0) {
            while (ld_acq(&g_seq[s]) != rs) { __nanosleep(32); }
            if (d != s) {
                while (ld_acq(&g_seq[d]) != rd) { __nanosleep(32); }
            }
        }
        __syncthreads();

        // stage inputs into shared memory
        if (tid < H) {
            float hs = g_h[(size_t)s * H + tid];
            float hd = g_h[(size_t)d * H + tid];
            sh_feat[0][tid]     = hd;  sh_feat[0][H + tid] = hs;   // msg for src: [hd, hs, ...]
            sh_feat[1][tid]     = hs;  sh_feat[1][H + tid] = hd;   // msg for dst: [hs, hd, ...]
            sh_c[0][tid] = g_c[(size_t)s * H + tid];
            sh_c[1][tid] = g_c[(size_t)d * H + tid];
        } else {
            int j = tid - H;
            if (j < EA) {
                float a = eattr[(size_t)e * EA + j];
                sh_feat[0][2 * H + j] = a;  sh_feat[1][2 * H + j] = a;
            } else {
                int k = j - EA;               // 0..31
                float t   = etime[e];
                float arg = fmaf(t, time_w[k], time_b[k]);   // match XLA fma contraction
                float te  = cosf(arg);                       // libm cosf: accurate range reduction
                sh_feat[0][2 * H + EA + k] = te;  sh_feat[1][2 * H + EA + k] = te;
            }
        }
        __syncthreads();

        // ---- message GEMV (dedup: each weight load feeds BOTH rows) ----
        // 128 threads = 32 col-pairs (cp) x 4 k-quarters (kq). 48 k per quarter.
        {
            int cp = tid & 31;          // columns 2cp, 2cp+1
            int kq = tid >> 5;          // k range [kq*48, kq*48+48)
            float a00 = 0.f, a01 = 0.f, a10 = 0.f, a11 = 0.f;
            int k0 = kq * 48;
#pragma unroll 8
            for (int k = k0; k < k0 + 48; k++) {
                float2 w = Wm2[k * 32 + cp];
                float f0 = sh_feat[0][k];
                float f1 = sh_feat[1][k];
                a00 = fmaf(f0, w.x, a00);
                a01 = fmaf(f0, w.y, a01);
                a10 = fmaf(f1, w.x, a10);
                a11 = fmaf(f1, w.y, a11);
            }
            ((float2*)sh_part[kq][0])[cp] = make_float2(a00, a01);
            ((float2*)sh_part[kq][1])[cp] = make_float2(a10, a11);
        }
        __syncthreads();
        // reduce partials + bias + relu
        {
            int r = tid >> 6, q = tid & 63;
            float m = b_msg[q] + sh_part[0][r][q] + sh_part[1][r][q]
                               + sh_part[2][r][q] + sh_part[3][r][q];
            sh_m[r][q] = fmaxf(m, 0.f);
        }
        __syncthreads();

        // ---- gates GEMV (dedup: each thread owns 2 cols, computes BOTH rows) ----
        // g[r] = m[r]@W_ih + hp[r]@W_hh + b ; thread t -> columns 2t, 2t+1 of 256
        {
            float2 ai0 = make_float2(0.f, 0.f), ai1 = make_float2(0.f, 0.f);
            float2 ah0 = make_float2(0.f, 0.f), ah1 = make_float2(0.f, 0.f);
#pragma unroll 4
            for (int k = 0; k < H; k++) {
                float2 wi = Wi2[k * 128 + tid];
                float2 wh = Wh2[k * 128 + tid];
                float m0 = sh_m[0][k], m1 = sh_m[1][k];
                float h0 = sh_feat[0][H + k], h1 = sh_feat[1][H + k];  // hp[0]=hs, hp[1]=hd
                ai0.x = fmaf(m0, wi.x, ai0.x);  ai0.y = fmaf(m0, wi.y, ai0.y);
                ai1.x = fmaf(m1, wi.x, ai1.x);  ai1.y = fmaf(m1, wi.y, ai1.y);
                ah0.x = fmaf(h0, wh.x, ah0.x);  ah0.y = fmaf(h0, wh.y, ah0.y);
                ah1.x = fmaf(h1, wh.x, ah1.x);  ah1.y = fmaf(h1, wh.y, ah1.y);
            }
            float2 b2 = Bl2[tid];
            ((float2*)sh_g[0])[tid] = make_float2(b2.x + ai0.x + ah0.x, b2.y + ai0.y + ah0.y);
            ((float2*)sh_g[1])[tid] = make_float2(b2.x + ai1.x + ah1.x, b2.y + ai1.y + ah1.y);
        }
        __syncthreads();

        // LSTM elementwise + writeback
        {
            int r = tid >> 6, j = tid & 63;
            float gi = sh_g[r][j];
            float gf = sh_g[r][H + j];
            float gg = sh_g[r][2 * H + j];
            float go = sh_g[r][3 * H + j];
            float cn = sigm(gf) * sh_c[r][j] + sigm(gi) * tanhf(gg);
            float hn = sigm(go) * tanhf(cn);
            if (r == 1 || d != s) {             // src==dst: dst row wins (rows identical anyway)
                int node = r ? d : s;
                g_h[(size_t)node * H + j] = hn;
                g_c[(size_t)node * H + j] = cn;
            }
        }
        __syncthreads();

        // publish
        if (tid == 0) {
            __threadfence();
            if (d == s) {
                st_rel(&g_seq[s], rs + 2);
            } else {
                st_rel(&g_seq[s], rs + 1);
                st_rel(&g_seq[d], rd + 1);
            }
        }
        __syncthreads();
    }
}

// ---------------- K4: fused embedding+classifier, 16 edges per block ----------------
#define LG_EDGES 16
__global__ void __launch_bounds__(128) k_logits_f(
    const float* __restrict__ x,
    const int*   __restrict__ ei,
    float*       __restrict__ out,
    int E, int A)
{
    __shared__ float sh_cat[2][FEAT];
    const int tid = threadIdx.x;
    const int base = blockIdx.x * LG_EDGES;

    for (int i = 0; i < LG_EDGES; i += 2) {
        // cooperatively stage two [h || x] rows
        for (int idx = tid; idx < 2 * FEAT; idx += 128) {
            int slot = idx / FEAT, j = idx % FEAT;
            int e2 = base + i + slot;
            float v = 0.f;
            if (e2 < E) {
                int dd = ei[E + e2];
                v = (j < H) ? g_h[(size_t)dd * H + j] : x[(size_t)dd * DF + (j - H)];
            }
            sh_cat[slot][j] = v;
        }
        __syncthreads();

        int slot = tid >> 6, q = tid & 63;
        int e2 = base + i + slot;
        if (q < A && e2 < E) {
            const float* cat = sh_cat[slot];
            float s0 = 0.f, s1 = 0.f, s2 = 0.f, s3 = 0.f;
#pragma unroll 4
            for (int k = 0; k < FEAT; k += 4) {
                s0 = fmaf(cat[k],     g_W1[k * A + q],       s0);
                s1 = fmaf(cat[k + 1], g_W1[(k + 1) * A + q], s1);
                s2 = fmaf(cat[k + 2], g_W1[(k + 2) * A + q], s2);
                s3 = fmaf(cat[k + 3], g_W1[(k + 3) * A + q], s3);
            }
            out[(size_t)e2 * A + q] = g_b1[q] + ((s0 + s1) + (s2 + s3));
        }
        __syncthreads();
    }
}

// ---------------- launch ----------------
extern "C" void kernel_launch(void* const* d_in, const int* in_sizes, int n_in,
                              void* d_out, int out_size)
{
    const float* x      = (const float*)d_in[0];
    const int*   ei     = (const int*)  d_in[1];   // [2,E]
    const float* eattr  = (const float*)d_in[2];
    const float* etime  = (const float*)d_in[3];
    const float* time_w = (const float*)d_in[4];
    const float* time_b = (const float*)d_in[5];
    const float* W_msg  = (const float*)d_in[6];
    const float* b_msg  = (const float*)d_in[7];
    const float* W_ih   = (const float*)d_in[8];
    const float* W_hh   = (const float*)d_in[9];
    const float* b_lstm = (const float*)d_in[10];
    const float* W_emb  = (const float*)d_in[11];
    const float* b_emb  = (const float*)d_in[12];
    const float* W_cls  = (const float*)d_in[13];
    const float* b_cls  = (const float*)d_in[14];

    const int E = in_sizes[3];             // edge_time element count
    const int A = out_size / E;            // num classes
    const int twoE = 2 * E;
    const int thr = 256;
    const int blks = (twoE + thr - 1) / thr;

    // Persistent-kernel grid: MUST be fully co-resident for the static
    // round-robin scheduler's forward-progress guarantee. Query the device.
    int dev = 0, nsm = 0, occ = 0;
    cudaGetDevice(&dev);
    cudaDeviceGetAttribute(&nsm, cudaDevAttrMultiProcessorCount, dev);
    cudaOccupancyMaxActiveBlocksPerMultiprocessor(&occ, k_events, 128, 0);
    if (nsm <= 0) nsm = 1;
    if (occ <= 0) occ = 1;
    int nblk = nsm * occ;
    if (nblk > E) nblk = E;

    const int fuse_total = FEAT * A;
    const int fuse_blks = (fuse_total + 127) / 128;
    const int lg_blks = (E + LG_EDGES - 1) / LG_EDGES;

    k_init<<<blks, thr>>>(ei, E);
    k_link<<<blks, thr>>>(ei, E);
    k_rank<<<blks, thr>>>(ei, E);
    k_fuse<<<fuse_blks, 128>>>(W_emb, b_emb, W_cls, b_cls, A);
    k_events<<<nblk, 128>>>(ei, eattr, etime, time_w, time_b,
                            W_msg, b_msg, W_ih, W_hh, b_lstm, E, nblk);
    k_logits_f<<<lg_blks, 128>>>(x, ei, (float*)d_out, E, A);
}